// round 13
// baseline (speedup 1.0000x reference)
#include <cuda_runtime.h>
#include <cuda_fp16.h>
#include <cstdint>

// Problem constants
#define NV 10242
#define NB 8
#define NC 128
#define NKF 9                          // slots in data layout
#define NSLOT 7                        // slots 7,8 are mask==0 for every vertex
#define M_TOTAL (NB * NV)              // 81936
#define TILE_M 192
#define NTILES ((M_TOTAL + TILE_M - 1) / TILE_M)   // 427
#define NCHUNKS (NSLOT * 2)            // 14 (slot x 64-channel half)
#define NTHREADS 640                   // 16 consumer warps + 4 producer warps
#define NCONS 512
#define NPROD 128

// stage: A 192x64 fp16 swizzled (24576B) | B 128x64 fp16 pre-swizzled (16384B)
#define A_BYTES 24576
#define B_OFF   24576
#define B_BYTES 16384
#define STAGE_BYTES 40960
#define NSTAGE 4
#define TBL_OFF (NSTAGE * STAGE_BYTES)            // 163840
#define SMEM_DYN (TBL_OFF + TILE_M * NSLOT * 4)   // 169216

// ---------------- device scratch (static globals: no allocation) -----------
__device__ __align__(16) __half g_wb[NCHUNKS * 128 * 64];  // pre-swizzled W

// ---------------- PTX helpers ----------------------------------------------
__device__ __forceinline__ uint32_t smem_u32(const void* p) {
    uint32_t a;
    asm("{ .reg .u64 t; cvta.to.shared.u64 t, %1; cvt.u32.u64 %0, t; }"
        : "=r"(a) : "l"(p));
    return a;
}
#define MBAR_INIT(a, c) \
    asm volatile("mbarrier.init.shared.b64 [%0], %1;" :: "r"(a), "r"(c) : "memory")
#define MBAR_ARRIVE(a) \
    asm volatile("mbarrier.arrive.release.cta.shared::cta.b64 _, [%0];" :: "r"(a) : "memory")
#define MBAR_EXPECT_TX(a, bytes) \
    asm volatile("mbarrier.arrive.expect_tx.shared.b64 _, [%0], %1;" \
                 :: "r"(a), "r"(bytes) : "memory")

__device__ __forceinline__ void bulk_g2s(uint32_t dst, const void* src,
                                         uint32_t bytes, uint32_t mbar) {
    asm volatile(
        "cp.async.bulk.shared::cta.global.mbarrier::complete_tx::bytes "
        "[%0], [%1], %2, [%3];"
        :: "r"(dst), "l"(src), "r"(bytes), "r"(mbar) : "memory");
}

__device__ __forceinline__ void mbar_wait(uint32_t mbar, uint32_t parity) {
    uint32_t done;
    asm volatile(
        "{\n\t.reg .pred p;\n\t"
        "mbarrier.try_wait.parity.acquire.cta.shared::cta.b64 p, [%1], %2;\n\t"
        "selp.b32 %0, 1, 0, p;\n\t}"
        : "=r"(done) : "r"(mbar), "r"(parity) : "memory");
    if (!done) {
        asm volatile(
            "{\n\t.reg .pred P1;\n\t"
            "WL_%=:\n\t"
            "mbarrier.try_wait.parity.acquire.cta.shared::cta.b64 P1, [%0], %1, 0x989680;\n\t"
            "@P1 bra.uni WD_%=;\n\t"
            "bra.uni WL_%=;\n\t"
            "WD_%=:\n\t}"
            :: "r"(mbar), "r"(parity) : "memory");
    }
}
__device__ __forceinline__ void ldsm4(uint32_t* r, uint32_t a) {
    asm volatile("ldmatrix.sync.aligned.m8n8.x4.shared.b16 {%0,%1,%2,%3}, [%4];"
                 : "=r"(r[0]), "=r"(r[1]), "=r"(r[2]), "=r"(r[3]) : "r"(a));
}
__device__ __forceinline__ void mma_f16(float* d, const uint32_t* a,
                                        uint32_t b0, uint32_t b1) {
    asm volatile(
        "mma.sync.aligned.m16n8k16.row.col.f32.f16.f16.f32 "
        "{%0,%1,%2,%3},{%4,%5,%6,%7},{%8,%9},{%0,%1,%2,%3};"
        : "+f"(d[0]), "+f"(d[1]), "+f"(d[2]), "+f"(d[3])
        : "r"(a[0]), "r"(a[1]), "r"(a[2]), "r"(a[3]), "r"(b0), "r"(b1));
}

// ---------------- prep kernel: W pack only ----------------------------------
#define PACK_BLOCKS ((NCHUNKS * 8192 + 255) / 256)             // 448

__global__ void prep_kernel(const float* __restrict__ w) {
    int i = blockIdx.x * 256 + threadIdx.x;
    if (i >= NCHUNKS * 8192) return;
    int t     = i & 8191;
    int n     = t >> 6;            // output channel (B row)
    int kk    = t & 63;            // channel within half
    int chunk = i >> 13;
    int slot  = chunk >> 1;
    int half  = (chunk & 1) * 64;
    float val = w[((size_t)n * NC + half + kk) * NKF + slot];
    int cc = kk >> 3;
    int dst = chunk * 8192 + n * 64 + ((cc ^ (n & 7)) << 3) + (kk & 7);
    g_wb[dst] = __float2half_rn(val);
}

// ---------------- main warp-specialized HMMA kernel --------------------------
__global__ void __launch_bounds__(NTHREADS, 1) ico_mma_kernel(
    const float* __restrict__ x,
    const float* __restrict__ bias,
    const int*   __restrict__ nidx,
    const float* __restrict__ nmask,
    float*       __restrict__ out) {
    extern __shared__ __align__(128) char smem[];
    const uint32_t sbase = smem_u32(smem);
    int* s_off = (int*)(smem + TBL_OFF);
    __shared__ __align__(8) uint64_t s_full[NSTAGE];
    __shared__ __align__(8) uint64_t s_empty[NSTAGE];

    const int tid  = threadIdx.x;
    const int lane = tid & 31;
    const int wid  = tid >> 5;
    const int tile_base = blockIdx.x * TILE_M;

    if (tid < NSTAGE) {
        // full: 128 producer release-arrives + 1 expect_tx (+16KB tx from bulk)
        MBAR_INIT(smem_u32(&s_full[tid]), NPROD + 1);
        MBAR_INIT(smem_u32(&s_empty[tid]), NCONS);
    }
    for (int e = tid; e < TILE_M * NSLOT; e += NTHREADS) {
        const int slot = e / TILE_M;
        const int r    = e - slot * TILE_M;
        const int g    = tile_base + r;
        int off = -1;
        if (g < M_TOTAL) {
            const int b = g / NV;
            const int v = g - b * NV;
            const float m = nmask[v * NKF + slot];
            const int  sv = nidx[v * NKF + slot];
            if (m != 0.f) off = (b * NV + sv) * (NC * 4);   // byte offset in fp32 x
        }
        s_off[e] = off;
    }
    __syncthreads();

    if (tid >= NCONS) {
        // === PRODUCER: 4 warps; A = LDG fp32 + cvt + swizzled STS; B bulk ===
        const int ptid = tid - NCONS;   // 0..127
        for (int it = 0; it < NCHUNKS; ++it) {
            const int s = it & (NSTAGE - 1);
            char* stageP = smem + s * STAGE_BYTES;
            const uint32_t stage = sbase + (uint32_t)s * STAGE_BYTES;
            const uint32_t fullb = smem_u32(&s_full[s]);
            mbar_wait(smem_u32(&s_empty[s]), ((it >> 2) + 1) & 1);

            // B: one 16KB bulk copy (pre-swizzled image), tx-tracked
            if (ptid == 0) {
                MBAR_EXPECT_TX(fullb, B_BYTES);
                bulk_g2s(stage + B_OFF, (const char*)g_wb + (size_t)it * B_BYTES,
                         B_BYTES, fullb);
            }

            const int slot  = it >> 1;
            const int halfF = (it & 1) * 256;   // fp32 byte offset of 64-ch half
            // A tile: gather fp32, convert to fp16, store swizzled
#pragma unroll
            for (int j = ptid; j < TILE_M * 8; j += NPROD) {   // 12 iters
                const int r = j >> 3;
                const int c = j & 7;                // 16B smem unit = 8 channels
                const int off = s_off[slot * TILE_M + r];
                uint4 outv = make_uint4(0, 0, 0, 0);
                if (off >= 0) {
                    const float4* src =
                        (const float4*)((const char*)x + off + halfF + c * 32);
                    const float4 f0 = __ldg(src);
                    const float4 f1 = __ldg(src + 1);
                    __half2 h0 = __float22half2_rn(make_float2(f0.x, f0.y));
                    __half2 h1 = __float22half2_rn(make_float2(f0.z, f0.w));
                    __half2 h2 = __float22half2_rn(make_float2(f1.x, f1.y));
                    __half2 h3 = __float22half2_rn(make_float2(f1.z, f1.w));
                    outv.x = *(uint32_t*)&h0;
                    outv.y = *(uint32_t*)&h1;
                    outv.z = *(uint32_t*)&h2;
                    outv.w = *(uint32_t*)&h3;
                }
                *(uint4*)(stageP + r * 128 + ((c ^ (r & 7)) << 4)) = outv;
            }
            MBAR_ARRIVE(fullb);    // release: orders the STS above
        }
        return;
    }

    // ================= CONSUMER: 16 warps, ldsm + MMA only ==================
    const int wm = (wid >> 2) * 48;      // warp M offset: 0/48/96/144
    const int wn = (wid & 3) * 32;       // warp N offset: 0..96

    float acc[3][4][4];
#pragma unroll
    for (int i = 0; i < 3; ++i)
#pragma unroll
        for (int j = 0; j < 4; ++j)
#pragma unroll
            for (int d = 0; d < 4; ++d) acc[i][j][d] = 0.f;

    // fully precomputed ldsm offsets (per ks)
    const int arow = lane & 15;
    const int csel = lane >> 4;
    uint32_t offA[4][3], offB[4][2];
#pragma unroll
    for (int ks = 0; ks < 4; ++ks) {
        const int cb = ks * 2 + csel;
#pragma unroll
        for (int i = 0; i < 3; ++i) {
            const int r = wm + i * 16 + arow;
            offA[ks][i] = (uint32_t)(r * 128 + ((cb ^ (r & 7)) << 4));
        }
#pragma unroll
        for (int jj = 0; jj < 2; ++jj) {
            const int r = wn + jj * 16 + arow;
            offB[ks][jj] = (uint32_t)(B_OFF + r * 128 + ((cb ^ (r & 7)) << 4));
        }
    }

    for (int it = 0; it < NCHUNKS; ++it) {
        const int s = it & (NSTAGE - 1);
        const uint32_t stage = sbase + (uint32_t)s * STAGE_BYTES;
        mbar_wait(smem_u32(&s_full[s]), (it >> 2) & 1);

        uint32_t aF[2][3][4], bF[2][2][4];
        auto load_frags = [&](int ks, int buf) {
#pragma unroll
            for (int jj = 0; jj < 2; ++jj)
                ldsm4(bF[buf][jj], stage + offB[ks][jj]);
#pragma unroll
            for (int i = 0; i < 3; ++i)
                ldsm4(aF[buf][i], stage + offA[ks][i]);
        };
        load_frags(0, 0);
#pragma unroll
        for (int ks = 0; ks < 4; ++ks) {
            const int cur = ks & 1;
            if (ks < 3) load_frags(ks + 1, cur ^ 1);
            if (ks == 3) MBAR_ARRIVE(smem_u32(&s_empty[s]));  // smem reads done
#pragma unroll
            for (int i = 0; i < 3; ++i)
#pragma unroll
                for (int j = 0; j < 4; ++j) {
                    const int jj = j >> 1, ss = j & 1;
                    mma_f16(acc[i][j], aF[cur][i], bF[cur][jj][ss], bF[cur][jj][ss + 2]);
                }
        }
    }

    // ---------------- epilogue: bias add + store (guard last tile) ----------
    const int colq = (lane & 3) * 2;
#pragma unroll
    for (int j = 0; j < 4; ++j) {
        const int col = wn + j * 8 + colq;
        const float b0 = __ldg(&bias[col]);
        const float b1 = __ldg(&bias[col + 1]);
#pragma unroll
        for (int i = 0; i < 3; ++i) {
            const int row0 = tile_base + wm + i * 16 + (lane >> 2);
            if (row0 < M_TOTAL) {
                float2 r0 = make_float2(acc[i][j][0] + b0, acc[i][j][1] + b1);
                *(float2*)(out + (size_t)row0 * NC + col) = r0;
            }
            if (row0 + 8 < M_TOTAL) {
                float2 r1 = make_float2(acc[i][j][2] + b0, acc[i][j][3] + b1);
                *(float2*)(out + (size_t)(row0 + 8) * NC + col) = r1;
            }
        }
    }
}

// ---------------- launch ------------------------------------------------------
extern "C" void kernel_launch(void* const* d_in, const int* in_sizes, int n_in,
                              void* d_out, int out_size) {
    const float* x     = (const float*)d_in[0];
    const float* w     = (const float*)d_in[1];
    const float* b     = (const float*)d_in[2];
    const int*   nidx  = (const int*)d_in[3];
    const float* nmask = (const float*)d_in[4];
    float*       out   = (float*)d_out;

    cudaFuncSetAttribute(ico_mma_kernel,
                         cudaFuncAttributeMaxDynamicSharedMemorySize, SMEM_DYN);

    prep_kernel<<<PACK_BLOCKS, 256>>>(w);
    ico_mma_kernel<<<NTILES, NTHREADS, SMEM_DYN>>>(x, b, nidx, nmask, out);
}

// round 14
// speedup vs baseline: 2.1285x; 2.1285x over previous
#include <cuda_runtime.h>
#include <cuda_fp16.h>
#include <cstdint>

// Problem constants
#define NV 10242
#define NB 8
#define NC 128
#define NKF 9                          // slots in data layout
#define NSLOT 7                        // slots 7,8 are mask==0 for every vertex
#define M_TOTAL (NB * NV)              // 81936
#define TILE_M 192
#define NTILES ((M_TOTAL + TILE_M - 1) / TILE_M)   // 427
#define NCHUNKS (NSLOT * 2)            // 14 (slot x 64-channel half)
#define NTHREADS 640                   // 16 consumer warps + 4 producer warps
#define NCONS 512
#define NPROD 128

// stage: A 192x64 fp16 swizzled (24576B) | B 128x64 fp16 pre-swizzled (16384B)
#define A_BYTES 24576
#define B_OFF   24576
#define B_BYTES 16384
#define STAGE_BYTES 40960
#define NSTAGE 4
#define TBL_OFF (NSTAGE * STAGE_BYTES)            // 163840
#define SMEM_DYN (TBL_OFF + TILE_M * NSLOT * 4)   // 169216

// ---------------- device scratch (static globals: no allocation) -----------
__device__ __align__(16) __half g_wb[NCHUNKS * 128 * 64];  // pre-swizzled W

// ---------------- PTX helpers ----------------------------------------------
__device__ __forceinline__ uint32_t smem_u32(const void* p) {
    uint32_t a;
    asm("{ .reg .u64 t; cvta.to.shared.u64 t, %1; cvt.u32.u64 %0, t; }"
        : "=r"(a) : "l"(p));
    return a;
}
#define MBAR_INIT(a, c) \
    asm volatile("mbarrier.init.shared.b64 [%0], %1;" :: "r"(a), "r"(c) : "memory")
#define MBAR_ARRIVE_REL(a) \
    asm volatile("mbarrier.arrive.release.cta.shared::cta.b64 _, [%0];" :: "r"(a) : "memory")
#define MBAR_ARRIVE(a) \
    asm volatile("mbarrier.arrive.shared.b64 _, [%0];" :: "r"(a) : "memory")
#define MBAR_EXPECT_TX(a, bytes) \
    asm volatile("mbarrier.arrive.expect_tx.shared.b64 _, [%0], %1;" \
                 :: "r"(a), "r"(bytes) : "memory")

__device__ __forceinline__ void bulk_g2s(uint32_t dst, const void* src,
                                         uint32_t bytes, uint32_t mbar) {
    asm volatile(
        "cp.async.bulk.shared::cta.global.mbarrier::complete_tx::bytes "
        "[%0], [%1], %2, [%3];"
        :: "r"(dst), "l"(src), "r"(bytes), "r"(mbar) : "memory");
}

__device__ __forceinline__ void mbar_wait(uint32_t mbar, uint32_t parity) {
    uint32_t done;
    asm volatile(
        "{\n\t.reg .pred p;\n\t"
        "mbarrier.try_wait.parity.acquire.cta.shared::cta.b64 p, [%1], %2;\n\t"
        "selp.b32 %0, 1, 0, p;\n\t}"
        : "=r"(done) : "r"(mbar), "r"(parity) : "memory");
    if (!done) {
        asm volatile(
            "{\n\t.reg .pred P1;\n\t"
            "WL_%=:\n\t"
            "mbarrier.try_wait.parity.acquire.cta.shared::cta.b64 P1, [%0], %1, 0x989680;\n\t"
            "@P1 bra.uni WD_%=;\n\t"
            "bra.uni WL_%=;\n\t"
            "WD_%=:\n\t}"
            :: "r"(mbar), "r"(parity) : "memory");
    }
}
__device__ __forceinline__ void ldsm4(uint32_t* r, uint32_t a) {
    asm volatile("ldmatrix.sync.aligned.m8n8.x4.shared.b16 {%0,%1,%2,%3}, [%4];"
                 : "=r"(r[0]), "=r"(r[1]), "=r"(r[2]), "=r"(r[3]) : "r"(a));
}
__device__ __forceinline__ void mma_f16(float* d, const uint32_t* a,
                                        uint32_t b0, uint32_t b1) {
    asm volatile(
        "mma.sync.aligned.m16n8k16.row.col.f32.f16.f16.f32 "
        "{%0,%1,%2,%3},{%4,%5,%6,%7},{%8,%9},{%0,%1,%2,%3};"
        : "+f"(d[0]), "+f"(d[1]), "+f"(d[2]), "+f"(d[3])
        : "r"(a[0]), "r"(a[1]), "r"(a[2]), "r"(a[3]), "r"(b0), "r"(b1));
}

// ---------------- prep kernel: W pack only ----------------------------------
#define PACK_BLOCKS ((NCHUNKS * 8192 + 255) / 256)             // 448

__global__ void prep_kernel(const float* __restrict__ w) {
    int i = blockIdx.x * 256 + threadIdx.x;
    if (i >= NCHUNKS * 8192) return;
    int t     = i & 8191;
    int n     = t >> 6;            // output channel (B row)
    int kk    = t & 63;            // channel within half
    int chunk = i >> 13;
    int slot  = chunk >> 1;
    int half  = (chunk & 1) * 64;
    float val = w[((size_t)n * NC + half + kk) * NKF + slot];
    int cc = kk >> 3;
    int dst = chunk * 8192 + n * 64 + ((cc ^ (n & 7)) << 3) + (kk & 7);
    g_wb[dst] = __float2half_rn(val);
}

// ---------------- main warp-specialized HMMA kernel --------------------------
__global__ void __launch_bounds__(NTHREADS, 1) ico_mma_kernel(
    const float* __restrict__ x,
    const float* __restrict__ bias,
    const int*   __restrict__ nidx,
    const float* __restrict__ nmask,
    float*       __restrict__ out) {
    extern __shared__ __align__(128) char smem[];
    const uint32_t sbase = smem_u32(smem);
    int* s_off = (int*)(smem + TBL_OFF);
    __shared__ __align__(8) uint64_t s_full[NSTAGE];
    __shared__ __align__(8) uint64_t s_empty[NSTAGE];

    const int tid  = threadIdx.x;
    const int lane = tid & 31;
    const int wid  = tid >> 5;
    const int tile_base = blockIdx.x * TILE_M;

    if (tid < NSTAGE) {
        // full: 128 producer release-arrives + 1 expect_tx (+16KB tx from bulk)
        MBAR_INIT(smem_u32(&s_full[tid]), NPROD + 1);
        MBAR_INIT(smem_u32(&s_empty[tid]), NCONS);
    }
    for (int e = tid; e < TILE_M * NSLOT; e += NTHREADS) {
        const int slot = e / TILE_M;
        const int r    = e - slot * TILE_M;
        const int g    = tile_base + r;
        int off = -1;
        if (g < M_TOTAL) {
            const int b = g / NV;
            const int v = g - b * NV;
            const float m = nmask[v * NKF + slot];
            const int  sv = nidx[v * NKF + slot];
            if (m != 0.f) off = (b * NV + sv) * (NC * 4);   // byte offset in fp32 x
        }
        s_off[e] = off;
    }
    __syncthreads();

    if (tid >= NCONS) {
        // === PRODUCER: 4 warps; A = batched LDG fp32 + cvt + STS; B bulk ===
        const int ptid = tid - NCONS;            // 0..127
        const int r0   = ptid >> 3;              // base row (steps by 16 per unit)
        const int cpos = ptid & 7;               // constant column unit
        const uint32_t dbase =                   // constant swizzled dst base
            (uint32_t)(r0 * 128 + ((cpos ^ (r0 & 7)) << 4));
        const int xoff_c = cpos * 32;            // fp32 byte offset of unit

        for (int it = 0; it < NCHUNKS; ++it) {
            const int s = it & (NSTAGE - 1);
            char* stageP = smem + s * STAGE_BYTES;
            const uint32_t stage = sbase + (uint32_t)s * STAGE_BYTES;
            const uint32_t fullb = smem_u32(&s_full[s]);
            mbar_wait(smem_u32(&s_empty[s]), ((it >> 2) + 1) & 1);

            // B: one 16KB bulk copy (pre-swizzled image), tx-tracked
            if (ptid == 0) {
                MBAR_EXPECT_TX(fullb, B_BYTES);
                bulk_g2s(stage + B_OFF, (const char*)g_wb + (size_t)it * B_BYTES,
                         B_BYTES, fullb);
            }

            const int slot  = it >> 1;
            const int halfF = (it & 1) * 256;   // fp32 byte offset of 64-ch half
            // preload the 12 row offsets for this thread (one LDS each)
            int offs[12];
#pragma unroll
            for (int k = 0; k < 12; ++k)
                offs[k] = s_off[slot * TILE_M + r0 + k * 16];

            // 3 batches x 4 units: 8 independent LDG.128 in flight per batch
#pragma unroll
            for (int b = 0; b < 3; ++b) {
                float4 f[4][2];
#pragma unroll
                for (int q = 0; q < 4; ++q) {
                    const int off = offs[b * 4 + q];
                    if (off >= 0) {
                        const float4* src = (const float4*)
                            ((const char*)x + off + halfF + xoff_c);
                        f[q][0] = __ldg(src);
                        f[q][1] = __ldg(src + 1);
                    } else {
                        f[q][0] = make_float4(0.f, 0.f, 0.f, 0.f);
                        f[q][1] = make_float4(0.f, 0.f, 0.f, 0.f);
                    }
                }
#pragma unroll
                for (int q = 0; q < 4; ++q) {
                    __half2 h0 = __float22half2_rn(make_float2(f[q][0].x, f[q][0].y));
                    __half2 h1 = __float22half2_rn(make_float2(f[q][0].z, f[q][0].w));
                    __half2 h2 = __float22half2_rn(make_float2(f[q][1].x, f[q][1].y));
                    __half2 h3 = __float22half2_rn(make_float2(f[q][1].z, f[q][1].w));
                    uint4 outv;
                    outv.x = *(uint32_t*)&h0;
                    outv.y = *(uint32_t*)&h1;
                    outv.z = *(uint32_t*)&h2;
                    outv.w = *(uint32_t*)&h3;
                    *(uint4*)(stageP + dbase + (b * 4 + q) * 2048) = outv;
                }
            }
            MBAR_ARRIVE_REL(fullb);    // release: orders the STS above
        }
        return;
    }

    // ================= CONSUMER: 16 warps, ldsm + MMA only ==================
    const int wm = (wid >> 2) * 48;      // warp M offset: 0/48/96/144
    const int wn = (wid & 3) * 32;       // warp N offset: 0..96

    float acc[3][4][4];
#pragma unroll
    for (int i = 0; i < 3; ++i)
#pragma unroll
        for (int j = 0; j < 4; ++j)
#pragma unroll
            for (int d = 0; d < 4; ++d) acc[i][j][d] = 0.f;

    // fully precomputed ldsm offsets (per ks)
    const int arow = lane & 15;
    const int csel = lane >> 4;
    uint32_t offA[4][3], offB[4][2];
#pragma unroll
    for (int ks = 0; ks < 4; ++ks) {
        const int cb = ks * 2 + csel;
#pragma unroll
        for (int i = 0; i < 3; ++i) {
            const int r = wm + i * 16 + arow;
            offA[ks][i] = (uint32_t)(r * 128 + ((cb ^ (r & 7)) << 4));
        }
#pragma unroll
        for (int jj = 0; jj < 2; ++jj) {
            const int r = wn + jj * 16 + arow;
            offB[ks][jj] = (uint32_t)(B_OFF + r * 128 + ((cb ^ (r & 7)) << 4));
        }
    }

    for (int it = 0; it < NCHUNKS; ++it) {
        const int s = it & (NSTAGE - 1);
        const uint32_t stage = sbase + (uint32_t)s * STAGE_BYTES;
        mbar_wait(smem_u32(&s_full[s]), (it >> 2) & 1);

        uint32_t aF[2][3][4], bF[2][2][4];
        auto load_frags = [&](int ks, int buf) {
#pragma unroll
            for (int jj = 0; jj < 2; ++jj)
                ldsm4(bF[buf][jj], stage + offB[ks][jj]);
#pragma unroll
            for (int i = 0; i < 3; ++i)
                ldsm4(aF[buf][i], stage + offA[ks][i]);
        };
        load_frags(0, 0);
#pragma unroll
        for (int ks = 0; ks < 4; ++ks) {
            const int cur = ks & 1;
            if (ks < 3) load_frags(ks + 1, cur ^ 1);
            if (ks == 3) MBAR_ARRIVE(smem_u32(&s_empty[s]));  // smem reads done
#pragma unroll
            for (int i = 0; i < 3; ++i)
#pragma unroll
                for (int j = 0; j < 4; ++j) {
                    const int jj = j >> 1, ss = j & 1;
                    mma_f16(acc[i][j], aF[cur][i], bF[cur][jj][ss], bF[cur][jj][ss + 2]);
                }
        }
    }

    // ---------------- epilogue: bias add + store (guard last tile) ----------
    const int colq = (lane & 3) * 2;
#pragma unroll
    for (int j = 0; j < 4; ++j) {
        const int col = wn + j * 8 + colq;
        const float b0 = __ldg(&bias[col]);
        const float b1 = __ldg(&bias[col + 1]);
#pragma unroll
        for (int i = 0; i < 3; ++i) {
            const int row0 = tile_base + wm + i * 16 + (lane >> 2);
            if (row0 < M_TOTAL) {
                float2 r0 = make_float2(acc[i][j][0] + b0, acc[i][j][1] + b1);
                *(float2*)(out + (size_t)row0 * NC + col) = r0;
            }
            if (row0 + 8 < M_TOTAL) {
                float2 r1 = make_float2(acc[i][j][2] + b0, acc[i][j][3] + b1);
                *(float2*)(out + (size_t)(row0 + 8) * NC + col) = r1;
            }
        }
    }
}

// ---------------- launch ------------------------------------------------------
extern "C" void kernel_launch(void* const* d_in, const int* in_sizes, int n_in,
                              void* d_out, int out_size) {
    const float* x     = (const float*)d_in[0];
    const float* w     = (const float*)d_in[1];
    const float* b     = (const float*)d_in[2];
    const int*   nidx  = (const int*)d_in[3];
    const float* nmask = (const float*)d_in[4];
    float*       out   = (float*)d_out;

    cudaFuncSetAttribute(ico_mma_kernel,
                         cudaFuncAttributeMaxDynamicSharedMemorySize, SMEM_DYN);

    prep_kernel<<<PACK_BLOCKS, 256>>>(w);
    ico_mma_kernel<<<NTILES, NTHREADS, SMEM_DYN>>>(x, b, nidx, nmask, out);
}

// round 15
// speedup vs baseline: 2.1942x; 1.0308x over previous
#include <cuda_runtime.h>
#include <cuda_fp16.h>
#include <cstdint>

// Problem constants
#define NV 10242
#define NB 8
#define NC 128
#define NKF 9                          // slots in data layout
#define NSLOT 7                        // slots 7,8 are mask==0 for every vertex
#define M_TOTAL (NB * NV)              // 81936 = 144 * 569 exactly
#define TILE_M 144
#define NTILES 569
#define NCHUNKS (NSLOT * 2)            // 14 (slot x 64-channel half)
#define NTHREADS 512                   // 12 consumer warps + 4 producer warps
#define NCONS 384
#define NPROD 128

// stage: A 144x64 fp16 swizzled (18432B) | B 128x64 fp16 pre-swizzled (16384B)
#define A_BYTES 18432
#define B_OFF   18432
#define B_BYTES 16384
#define STAGE_BYTES 34816
#define NSTAGE 4
#define TBL_OFF (NSTAGE * STAGE_BYTES)            // 139264
#define SMEM_DYN (TBL_OFF + TILE_M * NSLOT * 4)   // 143296

// ---------------- device scratch (static globals: no allocation) -----------
__device__ __align__(16) __half g_xh[NB * NV * NC];
__device__ __align__(16) __half g_wb[NCHUNKS * 128 * 64];  // pre-swizzled

// ---------------- PTX helpers ----------------------------------------------
__device__ __forceinline__ uint32_t smem_u32(const void* p) {
    uint32_t a;
    asm("{ .reg .u64 t; cvta.to.shared.u64 t, %1; cvt.u32.u64 %0, t; }"
        : "=r"(a) : "l"(p));
    return a;
}
__device__ __forceinline__ void cp16(uint32_t dst, const void* src, uint32_t sz) {
    asm volatile("cp.async.cg.shared.global [%0], [%1], 16, %2;"
                 :: "r"(dst), "l"(src), "r"(sz) : "memory");
}
#define MBAR_INIT(a, c) \
    asm volatile("mbarrier.init.shared.b64 [%0], %1;" :: "r"(a), "r"(c) : "memory")
#define MBAR_ARRIVE(a) \
    asm volatile("mbarrier.arrive.shared.b64 _, [%0];" :: "r"(a) : "memory")
#define MBAR_EXPECT_TX(a, bytes) \
    asm volatile("mbarrier.arrive.expect_tx.shared.b64 _, [%0], %1;" \
                 :: "r"(a), "r"(bytes) : "memory")
#define CPASYNC_ARRIVE(a) \
    asm volatile("cp.async.mbarrier.arrive.noinc.shared.b64 [%0];" :: "r"(a) : "memory")

__device__ __forceinline__ void bulk_g2s(uint32_t dst, const void* src,
                                         uint32_t bytes, uint32_t mbar) {
    asm volatile(
        "cp.async.bulk.shared::cta.global.mbarrier::complete_tx::bytes "
        "[%0], [%1], %2, [%3];"
        :: "r"(dst), "l"(src), "r"(bytes), "r"(mbar) : "memory");
}

__device__ __forceinline__ void mbar_wait(uint32_t mbar, uint32_t parity) {
    uint32_t done;
    asm volatile(
        "{\n\t.reg .pred p;\n\t"
        "mbarrier.try_wait.parity.acquire.cta.shared::cta.b64 p, [%1], %2;\n\t"
        "selp.b32 %0, 1, 0, p;\n\t}"
        : "=r"(done) : "r"(mbar), "r"(parity) : "memory");
    if (!done) {
        asm volatile(
            "{\n\t.reg .pred P1;\n\t"
            "WL_%=:\n\t"
            "mbarrier.try_wait.parity.acquire.cta.shared::cta.b64 P1, [%0], %1, 0x989680;\n\t"
            "@P1 bra.uni WD_%=;\n\t"
            "bra.uni WL_%=;\n\t"
            "WD_%=:\n\t}"
            :: "r"(mbar), "r"(parity) : "memory");
    }
}
__device__ __forceinline__ void ldsm4(uint32_t* r, uint32_t a) {
    asm volatile("ldmatrix.sync.aligned.m8n8.x4.shared.b16 {%0,%1,%2,%3}, [%4];"
                 : "=r"(r[0]), "=r"(r[1]), "=r"(r[2]), "=r"(r[3]) : "r"(a));
}
// f16-accumulate HMMA: D(f16x2 x2) = A*B + D
__device__ __forceinline__ void mma_f16h(uint32_t* d, const uint32_t* a,
                                         uint32_t b0, uint32_t b1) {
    asm volatile(
        "mma.sync.aligned.m16n8k16.row.col.f16.f16.f16.f16 "
        "{%0,%1},{%2,%3,%4,%5},{%6,%7},{%0,%1};"
        : "+r"(d[0]), "+r"(d[1])
        : "r"(a[0]), "r"(a[1]), "r"(a[2]), "r"(a[3]), "r"(b0), "r"(b1));
}

// ---------------- fused prep kernel -----------------------------------------
#define SPLIT_BLOCKS ((NB * NV * NC / 8 + 255) / 256)          // 641
#define PACK_BLOCKS  ((NCHUNKS * 8192 + 255) / 256)            // 448

__global__ void prep_kernel(const float* __restrict__ x,
                            const float* __restrict__ w) {
    if (blockIdx.x < SPLIT_BLOCKS) {
        int i = blockIdx.x * 256 + threadIdx.x;       // 8-float group
        const int n8 = (NB * NV * NC) / 8;
        if (i >= n8) return;
        float4 v0 = ((const float4*)x)[i * 2];
        float4 v1 = ((const float4*)x)[i * 2 + 1];
        float f[8] = {v0.x, v0.y, v0.z, v0.w, v1.x, v1.y, v1.z, v1.w};
        uint32_t hp[4];
#pragma unroll
        for (int j = 0; j < 4; ++j) {
            __half h0 = __float2half_rn(f[2 * j]);
            __half h1 = __float2half_rn(f[2 * j + 1]);
            hp[j] = (uint32_t)__half_as_ushort(h0) | ((uint32_t)__half_as_ushort(h1) << 16);
        }
        ((uint4*)g_xh)[i] = make_uint4(hp[0], hp[1], hp[2], hp[3]);
    } else {
        int i = (blockIdx.x - SPLIT_BLOCKS) * 256 + threadIdx.x;
        if (i >= NCHUNKS * 8192) return;
        int t     = i & 8191;
        int n     = t >> 6;            // output channel (B row)
        int kk    = t & 63;            // channel within half
        int chunk = i >> 13;
        int slot  = chunk >> 1;
        int half  = (chunk & 1) * 64;
        float val = w[((size_t)n * NC + half + kk) * NKF + slot];
        int cc = kk >> 3;
        int dst = chunk * 8192 + n * 64 + ((cc ^ (n & 7)) << 3) + (kk & 7);
        g_wb[dst] = __float2half_rn(val);
    }
}

// ---------------- main warp-specialized HMMA kernel --------------------------
__global__ void __launch_bounds__(NTHREADS, 1) ico_mma_kernel(
    const float* __restrict__ bias,
    const int*   __restrict__ nidx,
    const float* __restrict__ nmask,
    float*       __restrict__ out) {
    extern __shared__ __align__(128) char smem[];
    const uint32_t sbase = smem_u32(smem);
    int* s_off = (int*)(smem + TBL_OFF);
    __shared__ __align__(8) uint64_t s_full[NSTAGE];
    __shared__ __align__(8) uint64_t s_empty[NSTAGE];

    const int tid  = threadIdx.x;
    const int lane = tid & 31;
    const int wid  = tid >> 5;
    const int tile_base = blockIdx.x * TILE_M;

    if (tid < NSTAGE) {
        // full: 128 cp.async arrivals + 1 expect_tx arrival (+16KB tx from bulk)
        MBAR_INIT(smem_u32(&s_full[tid]), NPROD + 1);
        MBAR_INIT(smem_u32(&s_empty[tid]), NCONS);
    }
    for (int e = tid; e < TILE_M * NSLOT; e += NTHREADS) {
        const int slot = e / TILE_M;
        const int r    = e - slot * TILE_M;
        const int g    = tile_base + r;
        const int b    = g / NV;
        const int v    = g - b * NV;
        const float m  = nmask[v * NKF + slot];
        const int  sv  = nidx[v * NKF + slot];
        s_off[e] = (m != 0.f) ? (b * NV + sv) * (NC * 2) : -1;
    }
    __syncthreads();

    if (tid >= NCONS) {
        // ========= PRODUCER: 4 warps; A via LDGSTS, B via 16KB bulk =========
        const int ptid = tid - NCONS;   // 0..127
        for (int it = 0; it < NCHUNKS; ++it) {
            const int s = it & (NSTAGE - 1);
            const uint32_t stage = sbase + (uint32_t)s * STAGE_BYTES;
            const uint32_t fullb = smem_u32(&s_full[s]);
            mbar_wait(smem_u32(&s_empty[s]), ((it >> 2) + 1) & 1);

            // B: one 16KB bulk copy (pre-swizzled image), tx-tracked
            if (ptid == 0) {
                MBAR_EXPECT_TX(fullb, B_BYTES);
                bulk_g2s(stage + B_OFF, (const char*)g_wb + (size_t)it * B_BYTES,
                         B_BYTES, fullb);
            }

            const int slot  = it >> 1;
            const int halfB = (it & 1) * 128;   // byte offset within x row
            // A tile: masked gather, zero-fill via src-size=0
#pragma unroll
            for (int j = ptid; j < TILE_M * 8; j += NPROD) {   // 9 iters
                const int r = j >> 3;
                const int c = j & 7;
                const int off = s_off[slot * TILE_M + r];
                const uint32_t sz = (off >= 0) ? 16u : 0u;
                const int ofc = (off >= 0 ? off : 0) + halfB + c * 16;
                cp16(stage + r * 128 + ((c ^ (r & 7)) << 4),
                     (const char*)g_xh + ofc, sz);
            }
            CPASYNC_ARRIVE(fullb);   // arrives when this thread's cp.asyncs land
        }
        return;
    }

    // ======== CONSUMER: 12 warps; f16-acc HMMA + per-chunk f32 promote ======
    const int wm = (wid >> 2) * 48;      // warp M offset: 0/48/96
    const int wn = (wid & 3) * 32;       // warp N offset: 0..96

    float acc[3][4][4];
#pragma unroll
    for (int i = 0; i < 3; ++i)
#pragma unroll
        for (int j = 0; j < 4; ++j)
#pragma unroll
            for (int d = 0; d < 4; ++d) acc[i][j][d] = 0.f;

    // ldsm row bases + swizzle keys (offset recomputed per ks: saves regs)
    const int arow = lane & 15;
    const int csel = lane >> 4;
    uint32_t aBase[3], bBase[2];
    int aKey[3], bKey[2];
#pragma unroll
    for (int i = 0; i < 3; ++i) {
        const int r = wm + i * 16 + arow;
        aBase[i] = (uint32_t)(r * 128);
        aKey[i] = r & 7;
    }
#pragma unroll
    for (int jj = 0; jj < 2; ++jj) {
        const int r = wn + jj * 16 + arow;
        bBase[jj] = (uint32_t)(B_OFF + r * 128);
        bKey[jj] = r & 7;
    }

    for (int it = 0; it < NCHUNKS; ++it) {
        const int s = it & (NSTAGE - 1);
        const uint32_t stage = sbase + (uint32_t)s * STAGE_BYTES;
        mbar_wait(smem_u32(&s_full[s]), (it >> 2) & 1);

        // f16 chunk accumulators (zeroed each chunk)
        uint32_t hacc[3][4][2];
#pragma unroll
        for (int i = 0; i < 3; ++i)
#pragma unroll
            for (int j = 0; j < 4; ++j) {
                hacc[i][j][0] = 0u;
                hacc[i][j][1] = 0u;
            }

#pragma unroll
        for (int ks = 0; ks < 4; ++ks) {
            const int cb = ks * 2 + csel;
            uint32_t aF[3][4], bF[2][4];
#pragma unroll
            for (int jj = 0; jj < 2; ++jj)
                ldsm4(bF[jj], stage + bBase[jj] + (uint32_t)((cb ^ bKey[jj]) << 4));
#pragma unroll
            for (int i = 0; i < 3; ++i)
                ldsm4(aF[i], stage + aBase[i] + (uint32_t)((cb ^ aKey[i]) << 4));
            if (ks == 3) MBAR_ARRIVE(smem_u32(&s_empty[s]));  // smem reads done
#pragma unroll
            for (int i = 0; i < 3; ++i)
#pragma unroll
                for (int j = 0; j < 4; ++j) {
                    const int jj = j >> 1, ss = j & 1;
                    mma_f16h(hacc[i][j], aF[i], bF[jj][ss], bF[jj][ss + 2]);
                }
        }

        // promote chunk result to f32 master accumulators
#pragma unroll
        for (int i = 0; i < 3; ++i)
#pragma unroll
            for (int j = 0; j < 4; ++j) {
                float2 lo = __half22float2(*(__half2*)&hacc[i][j][0]);
                float2 hi = __half22float2(*(__half2*)&hacc[i][j][1]);
                acc[i][j][0] += lo.x;
                acc[i][j][1] += lo.y;
                acc[i][j][2] += hi.x;
                acc[i][j][3] += hi.y;
            }
    }

    // ---------------- epilogue: bias add + store (M exact: no guards) -------
    const int colq = (lane & 3) * 2;
#pragma unroll
    for (int j = 0; j < 4; ++j) {
        const int col = wn + j * 8 + colq;
        const float b0 = __ldg(&bias[col]);
        const float b1 = __ldg(&bias[col + 1]);
#pragma unroll
        for (int i = 0; i < 3; ++i) {
            const int row0 = tile_base + wm + i * 16 + (lane >> 2);
            float2 r0 = make_float2(acc[i][j][0] + b0, acc[i][j][1] + b1);
            *(float2*)(out + (size_t)row0 * NC + col) = r0;
            float2 r1 = make_float2(acc[i][j][2] + b0, acc[i][j][3] + b1);
            *(float2*)(out + (size_t)(row0 + 8) * NC + col) = r1;
        }
    }
}

// ---------------- launch ------------------------------------------------------
extern "C" void kernel_launch(void* const* d_in, const int* in_sizes, int n_in,
                              void* d_out, int out_size) {
    const float* x     = (const float*)d_in[0];
    const float* w     = (const float*)d_in[1];
    const float* b     = (const float*)d_in[2];
    const int*   nidx  = (const int*)d_in[3];
    const float* nmask = (const float*)d_in[4];
    float*       out   = (float*)d_out;

    cudaFuncSetAttribute(ico_mma_kernel,
                         cudaFuncAttributeMaxDynamicSharedMemorySize, SMEM_DYN);

    prep_kernel<<<SPLIT_BLOCKS + PACK_BLOCKS, 256>>>(x, w);
    ico_mma_kernel<<<NTILES, NTHREADS, SMEM_DYN>>>(b, nidx, nmask, out);
}

// round 16
// speedup vs baseline: 2.5757x; 1.1739x over previous
#include <cuda_runtime.h>
#include <cuda_fp16.h>
#include <cstdint>

// Problem constants
#define NV 10242
#define NB 8
#define NC 128
#define NKF 9                          // slots in data layout
#define NSLOT 7                        // slots 7,8 are mask==0 for every vertex
#define M_TOTAL (NB * NV)              // 81936 = 144 * 569 exactly
#define TILE_M 144
#define NTILES 569
#define NCHUNKS (NSLOT * 2)            // 14 (slot x 64-channel half)
#define NTHREADS 512                   // 12 consumer warps + 4 producer warps
#define NCONS 384
#define NPROD 128
#define GRID_MAIN 148                  // min sm_103a SM count: never oversubscribe

// stage: A 144x64 fp16 swizzled (18432B) | B 128x64 fp16 pre-swizzled (16384B)
#define A_BYTES 18432
#define B_OFF   18432
#define B_BYTES 16384
#define STAGE_BYTES 34816
#define NSTAGE 4
#define TBL_OFF (NSTAGE * STAGE_BYTES)            // 139264
#define SMEM_DYN (TBL_OFF + TILE_M * NSLOT * 4)   // 143296

// ---------------- device scratch (static globals: no allocation) -----------
__device__ __align__(16) __half g_xh[NB * NV * NC];
__device__ __align__(16) __half g_wb[NCHUNKS * 128 * 64];  // pre-swizzled

// ---------------- PTX helpers ----------------------------------------------
__device__ __forceinline__ uint32_t smem_u32(const void* p) {
    uint32_t a;
    asm("{ .reg .u64 t; cvta.to.shared.u64 t, %1; cvt.u32.u64 %0, t; }"
        : "=r"(a) : "l"(p));
    return a;
}
__device__ __forceinline__ void cp16(uint32_t dst, const void* src, uint32_t sz) {
    asm volatile("cp.async.cg.shared.global [%0], [%1], 16, %2;"
                 :: "r"(dst), "l"(src), "r"(sz) : "memory");
}
#define MBAR_INIT(a, c) \
    asm volatile("mbarrier.init.shared.b64 [%0], %1;" :: "r"(a), "r"(c) : "memory")
#define MBAR_ARRIVE(a) \
    asm volatile("mbarrier.arrive.shared.b64 _, [%0];" :: "r"(a) : "memory")
#define MBAR_EXPECT_TX(a, bytes) \
    asm volatile("mbarrier.arrive.expect_tx.shared.b64 _, [%0], %1;" \
                 :: "r"(a), "r"(bytes) : "memory")
#define CPASYNC_ARRIVE(a) \
    asm volatile("cp.async.mbarrier.arrive.noinc.shared.b64 [%0];" :: "r"(a) : "memory")
#define PROD_BAR() \
    asm volatile("bar.sync 1, %0;" :: "n"(NPROD) : "memory")

__device__ __forceinline__ void bulk_g2s(uint32_t dst, const void* src,
                                         uint32_t bytes, uint32_t mbar) {
    asm volatile(
        "cp.async.bulk.shared::cta.global.mbarrier::complete_tx::bytes "
        "[%0], [%1], %2, [%3];"
        :: "r"(dst), "l"(src), "r"(bytes), "r"(mbar) : "memory");
}

__device__ __forceinline__ void mbar_wait(uint32_t mbar, uint32_t parity) {
    uint32_t done;
    asm volatile(
        "{\n\t.reg .pred p;\n\t"
        "mbarrier.try_wait.parity.acquire.cta.shared::cta.b64 p, [%1], %2;\n\t"
        "selp.b32 %0, 1, 0, p;\n\t}"
        : "=r"(done) : "r"(mbar), "r"(parity) : "memory");
    if (!done) {
        asm volatile(
            "{\n\t.reg .pred P1;\n\t"
            "WL_%=:\n\t"
            "mbarrier.try_wait.parity.acquire.cta.shared::cta.b64 P1, [%0], %1, 0x989680;\n\t"
            "@P1 bra.uni WD_%=;\n\t"
            "bra.uni WL_%=;\n\t"
            "WD_%=:\n\t}"
            :: "r"(mbar), "r"(parity) : "memory");
    }
}
__device__ __forceinline__ void ldsm4(uint32_t* r, uint32_t a) {
    asm volatile("ldmatrix.sync.aligned.m8n8.x4.shared.b16 {%0,%1,%2,%3}, [%4];"
                 : "=r"(r[0]), "=r"(r[1]), "=r"(r[2]), "=r"(r[3]) : "r"(a));
}
__device__ __forceinline__ void mma_f16(float* d, const uint32_t* a,
                                        uint32_t b0, uint32_t b1) {
    asm volatile(
        "mma.sync.aligned.m16n8k16.row.col.f32.f16.f16.f32 "
        "{%0,%1,%2,%3},{%4,%5,%6,%7},{%8,%9},{%0,%1,%2,%3};"
        : "+f"(d[0]), "+f"(d[1]), "+f"(d[2]), "+f"(d[3])
        : "r"(a[0]), "r"(a[1]), "r"(a[2]), "r"(a[3]), "r"(b0), "r"(b1));
}

// ---------------- fused prep kernel (high-ILP split + W pack) ---------------
#define SPLIT_BLOCKS ((NB * NV * NC / 16 + 255) / 256)         // 2561
#define PACK_BLOCKS  ((NCHUNKS * 8192 + 255) / 256)            // 448

__global__ void prep_kernel(const float* __restrict__ x,
                            const float* __restrict__ w) {
    if (blockIdx.x < SPLIT_BLOCKS) {
        int i = blockIdx.x * 256 + threadIdx.x;       // 16-float group
        const int n16 = (NB * NV * NC) / 16;
        if (i >= n16) return;
        float4 v[4];
#pragma unroll
        for (int q = 0; q < 4; ++q) v[q] = ((const float4*)x)[i * 4 + q];  // MLP 4
        uint4 o[2];
#pragma unroll
        for (int q = 0; q < 4; ++q) {
            __half2 h0 = __float22half2_rn(make_float2(v[q].x, v[q].y));
            __half2 h1 = __float22half2_rn(make_float2(v[q].z, v[q].w));
            ((uint32_t*)o)[q * 2]     = *(uint32_t*)&h0;
            ((uint32_t*)o)[q * 2 + 1] = *(uint32_t*)&h1;
        }
        ((uint4*)g_xh)[i * 2]     = o[0];
        ((uint4*)g_xh)[i * 2 + 1] = o[1];
    } else {
        int i = (blockIdx.x - SPLIT_BLOCKS) * 256 + threadIdx.x;
        if (i >= NCHUNKS * 8192) return;
        int t     = i & 8191;
        int n     = t >> 6;            // output channel (B row)
        int kk    = t & 63;            // channel within half
        int chunk = i >> 13;
        int slot  = chunk >> 1;
        int half  = (chunk & 1) * 64;
        float val = w[((size_t)n * NC + half + kk) * NKF + slot];
        int cc = kk >> 3;
        int dst = chunk * 8192 + n * 64 + ((cc ^ (n & 7)) << 3) + (kk & 7);
        g_wb[dst] = __float2half_rn(val);
    }
}

// ---------------- persistent warp-specialized HMMA kernel --------------------
__global__ void __launch_bounds__(NTHREADS, 1) ico_mma_kernel(
    const float* __restrict__ bias,
    const int*   __restrict__ nidx,
    const float* __restrict__ nmask,
    float*       __restrict__ out) {
    extern __shared__ __align__(128) char smem[];
    const uint32_t sbase = smem_u32(smem);
    int* s_off = (int*)(smem + TBL_OFF);        // producer-private gather table
    __shared__ __align__(8) uint64_t s_full[NSTAGE];
    __shared__ __align__(8) uint64_t s_empty[NSTAGE];

    const int tid  = threadIdx.x;
    const int lane = tid & 31;
    const int wid  = tid >> 5;

    // tiles for this CTA: blockIdx.x, +148, +296, +444
    const int ntiles = (blockIdx.x < NTILES - 3 * GRID_MAIN) ? 4 : 3;

    if (tid < NSTAGE) {
        // full: 128 cp.async arrivals + 1 expect_tx arrival (+16KB tx from bulk)
        MBAR_INIT(smem_u32(&s_full[tid]), NPROD + 1);
        MBAR_INIT(smem_u32(&s_empty[tid]), NCONS);
    }
    __syncthreads();

    if (tid >= NCONS) {
        // ===== PRODUCER: 4 warps; builds s_off per tile, then 14 chunks =====
        const int ptid = tid - NCONS;   // 0..127
        int gc = 0;                     // global chunk counter (parity source)
        for (int tt = 0; tt < ntiles; ++tt) {
            const int tile_base = (blockIdx.x + tt * GRID_MAIN) * TILE_M;
            // build gather table (producers are the only readers/writers)
#pragma unroll
            for (int e = ptid; e < TILE_M * NSLOT; e += NPROD) {  // 8 iters
                const int slot = e / TILE_M;
                const int r    = e - slot * TILE_M;
                const int g    = tile_base + r;
                const int b    = g / NV;
                const int v    = g - b * NV;
                const float m  = nmask[v * NKF + slot];
                const int  sv  = nidx[v * NKF + slot];
                s_off[e] = (m != 0.f) ? (b * NV + sv) * (NC * 2) : -1;
            }
            PROD_BAR();   // table visible to all producer threads

            for (int it = 0; it < NCHUNKS; ++it, ++gc) {
                const int s = gc & (NSTAGE - 1);
                const uint32_t stage = sbase + (uint32_t)s * STAGE_BYTES;
                const uint32_t fullb = smem_u32(&s_full[s]);
                mbar_wait(smem_u32(&s_empty[s]), ((gc >> 2) + 1) & 1);

                // B: one 16KB bulk copy (pre-swizzled image), tx-tracked
                if (ptid == 0) {
                    MBAR_EXPECT_TX(fullb, B_BYTES);
                    bulk_g2s(stage + B_OFF,
                             (const char*)g_wb + (size_t)it * B_BYTES,
                             B_BYTES, fullb);
                }

                const int slot  = it >> 1;
                const int halfB = (it & 1) * 128;  // byte offset within x row
                // A tile: masked gather, zero-fill via src-size=0
#pragma unroll
                for (int j = ptid; j < TILE_M * 8; j += NPROD) {  // 9 iters
                    const int r = j >> 3;
                    const int c = j & 7;
                    const int off = s_off[slot * TILE_M + r];
                    const uint32_t sz = (off >= 0) ? 16u : 0u;
                    const int ofc = (off >= 0 ? off : 0) + halfB + c * 16;
                    cp16(stage + r * 128 + ((c ^ (r & 7)) << 4),
                         (const char*)g_xh + ofc, sz);
                }
                CPASYNC_ARRIVE(fullb);  // arrives when this thread's copies land
            }
            PROD_BAR();   // all issues done before next tile's table overwrite
        }
        return;
    }

    // ========== CONSUMER: 12 warps, ldsm + MMA; epilogue per tile ===========
    const int wm = (wid >> 2) * 48;      // warp M offset: 0/48/96
    const int wn = (wid & 3) * 32;       // warp N offset: 0..96

    // fully precomputed ldsm offsets (per ks)
    const int arow = lane & 15;
    const int csel = lane >> 4;
    uint32_t offA[4][3], offB[4][2];
#pragma unroll
    for (int ks = 0; ks < 4; ++ks) {
        const int cb = ks * 2 + csel;
#pragma unroll
        for (int i = 0; i < 3; ++i) {
            const int r = wm + i * 16 + arow;
            offA[ks][i] = (uint32_t)(r * 128 + ((cb ^ (r & 7)) << 4));
        }
#pragma unroll
        for (int jj = 0; jj < 2; ++jj) {
            const int r = wn + jj * 16 + arow;
            offB[ks][jj] = (uint32_t)(B_OFF + r * 128 + ((cb ^ (r & 7)) << 4));
        }
    }

    int gc = 0;
    for (int tt = 0; tt < ntiles; ++tt) {
        const int tile_base = (blockIdx.x + tt * GRID_MAIN) * TILE_M;

        float acc[3][4][4];
#pragma unroll
        for (int i = 0; i < 3; ++i)
#pragma unroll
            for (int j = 0; j < 4; ++j)
#pragma unroll
                for (int d = 0; d < 4; ++d) acc[i][j][d] = 0.f;

        for (int it = 0; it < NCHUNKS; ++it, ++gc) {
            const int s = gc & (NSTAGE - 1);
            const uint32_t stage = sbase + (uint32_t)s * STAGE_BYTES;
            mbar_wait(smem_u32(&s_full[s]), (gc >> 2) & 1);

            uint32_t aF[2][3][4], bF[2][2][4];
            auto load_frags = [&](int ks, int buf) {
#pragma unroll
                for (int jj = 0; jj < 2; ++jj)
                    ldsm4(bF[buf][jj], stage + offB[ks][jj]);
#pragma unroll
                for (int i = 0; i < 3; ++i)
                    ldsm4(aF[buf][i], stage + offA[ks][i]);
            };
            load_frags(0, 0);
#pragma unroll
            for (int ks = 0; ks < 4; ++ks) {
                const int cur = ks & 1;
                if (ks < 3) load_frags(ks + 1, cur ^ 1);
                if (ks == 3) MBAR_ARRIVE(smem_u32(&s_empty[s]));  // reads done
#pragma unroll
                for (int i = 0; i < 3; ++i)
#pragma unroll
                    for (int j = 0; j < 4; ++j) {
                        const int jj = j >> 1, ss = j & 1;
                        mma_f16(acc[i][j], aF[cur][i],
                                bF[cur][jj][ss], bF[cur][jj][ss + 2]);
                    }
            }
        }

        // epilogue (overlaps producer's next-tile gather): M exact, no guards
        const int colq = (lane & 3) * 2;
#pragma unroll
        for (int j = 0; j < 4; ++j) {
            const int col = wn + j * 8 + colq;
            const float b0 = __ldg(&bias[col]);
            const float b1 = __ldg(&bias[col + 1]);
#pragma unroll
            for (int i = 0; i < 3; ++i) {
                const int row0 = tile_base + wm + i * 16 + (lane >> 2);
                float2 r0 = make_float2(acc[i][j][0] + b0, acc[i][j][1] + b1);
                *(float2*)(out + (size_t)row0 * NC + col) = r0;
                float2 r1 = make_float2(acc[i][j][2] + b0, acc[i][j][3] + b1);
                *(float2*)(out + (size_t)(row0 + 8) * NC + col) = r1;
            }
        }
    }
}

// ---------------- launch ------------------------------------------------------
extern "C" void kernel_launch(void* const* d_in, const int* in_sizes, int n_in,
                              void* d_out, int out_size) {
    const float* x     = (const float*)d_in[0];
    const float* w     = (const float*)d_in[1];
    const float* b     = (const float*)d_in[2];
    const int*   nidx  = (const int*)d_in[3];
    const float* nmask = (const float*)d_in[4];
    float*       out   = (float*)d_out;

    cudaFuncSetAttribute(ico_mma_kernel,
                         cudaFuncAttributeMaxDynamicSharedMemorySize, SMEM_DYN);

    prep_kernel<<<SPLIT_BLOCKS + PACK_BLOCKS, 256>>>(x, w);
    ico_mma_kernel<<<GRID_MAIN, NTHREADS, SMEM_DYN>>>(b, nidx, nmask, out);
}